// round 12
// baseline (speedup 1.0000x reference)
#include <cuda_runtime.h>

#define Nn 5000
#define Ee 80000
#define FIN 32
#define Dd 64
#define P1n 256
#define P2n 32
#define Hh 256
#define Mm 5288
#define ELLW 64
#define SCALE 1.4763057f
#define M1 (256.f/5000.f)
#define KSPLIT 192
#define CHUNK 27
#define E1ROWS (KSPLIT * CHUNK)   // 5184 padded rows

typedef unsigned long long u64;

// ---------------- packed f32x2 helpers ----------------
__device__ __forceinline__ void fma2(u64& acc, u64 b, u64 a) {
    asm("fma.rn.f32x2 %0, %1, %2, %0;" : "+l"(acc) : "l"(b), "l"(a));
}
__device__ __forceinline__ u64 pk2(float lo, float hi) {
    u64 r; asm("mov.b64 %0, {%1, %2};" : "=l"(r) : "f"(lo), "f"(hi)); return r;
}
__device__ __forceinline__ void unpk(u64 v, float& a, float& b) {
    asm("mov.b64 {%0, %1}, %2;" : "=f"(a), "=f"(b) : "l"(v));
}
__device__ __forceinline__ float sum2(u64 v) {
    float a, b; unpk(v, a, b); return a + b;
}
__device__ __forceinline__ void red4(float* p, float a, float b, float c, float d) {
    asm volatile("red.global.add.v4.f32 [%0], {%1,%2,%3,%4};"
                 :: "l"(p), "f"(a), "f"(b), "f"(c), "f"(d) : "memory");
}

// ---------------- scratch (static, no allocation) ----------------
__device__ __align__(16) float g_z[Nn * Dd];
__device__ __align__(16) float g_XW1[Nn * Dd];
__device__ __align__(16) float g_E1[E1ROWS * P1n];  // exp(P1), padded
__device__ __align__(16) float g_AS1[Nn * P1n];     // A @ E1 (unscaled)
__device__ __align__(16) float g_ze1[Nn * Dd];
__device__ __align__(16) float g_U[5056 * Dd];      // AS1 @ (D_iz x1)
__device__ int g_cnt[Nn];
__device__ int g_ell[Nn * ELLW];
__device__ float g_colE[P1n], g_colEV[P1n], g_invZ[P1n];
__device__ __align__(16) float g_x1[P1n * Dd];
__device__ float g_y1[P1n];
__device__ __align__(16) float g_V[P1n * Dd];       // E1^T U (unscaled)
__device__ __align__(16) float g_S2[P1n * P2n];
__device__ float g_c[Hh], g_q[Hh], g_w0[Hh];
__device__ float g_acc[4];   // [0]=ent, [1]=sum(u-y)^2, [2]=sum(res^2)
__device__ unsigned int g_done;

// ---------------- kernel 1: zero accumulators + decoder prep ----------------
__global__ void prep(const float* __restrict__ t, const float* __restrict__ W1,
                     const float* __restrict__ b1) {
    int i = blockIdx.x * blockDim.x + threadIdx.x;
    int st = gridDim.x * blockDim.x;
    for (int k = i; k < Nn; k += st) g_cnt[k] = 0;
    for (int k = i; k < P1n; k += st) { g_colE[k] = 0.f; g_colEV[k] = 0.f; g_y1[k] = 0.f; }
    for (int k = i; k < P1n * Dd; k += st) { g_x1[k] = 0.f; g_V[k] = 0.f; }
    if (i == 0) { g_acc[0] = g_acc[1] = g_acc[2] = g_acc[3] = 0.f; g_done = 0u; }
    if (blockIdx.x == 0) {
        int h = threadIdx.x;
        float t0 = t[0];
        float tx[6];
        tx[0] = t0 * 1e-2f;
        tx[1] = t0 * 1e-3f;
        tx[2] = t0 * 1e-4f;
        tx[3] = logf(t0 * 100.f + 1.f);
        tx[4] = logf(t0 * 10.f + 1.f);
        tx[5] = logf(t0 + 1.f);
        float c = b1[h];
#pragma unroll
        for (int k = 0; k < 6; k++) c += W1[k * Hh + h] * tx[k];
        float q = 0.f;
#pragma unroll
        for (int k = 1; k < 9; k++) { float w = W1[k * Hh + h]; q += w * w; }
        g_c[h] = c; g_q[h] = q; g_w0[h] = W1[h];
    }
}

// ---------------- kernel 2: encode (blocks 0..156) + edge ELL scatter ----------------
__global__ void __launch_bounds__(256) enc_edge(
    const float* __restrict__ x0, const float* __restrict__ Wenc,
    const float* __restrict__ Wemb, const float* __restrict__ Wp,
    const int* __restrict__ adj) {
    int tid = threadIdx.x;
    if (blockIdx.x >= 157) {
        int e = (blockIdx.x - 157) * 256 + tid;
        if (e < Ee) {
            int r0 = adj[e], r1 = adj[Ee + e];
            int pos = atomicAdd(&g_cnt[r0], 1);
            if (pos < ELLW) g_ell[r0 * ELLW + pos] = r1;
        }
        return;
    }
    __shared__ float xsh[32][FIN];
    __shared__ __align__(16) float zsh[32][Dd];
    int r0 = blockIdx.x * 32;
    for (int idx = tid; idx < 32 * FIN; idx += 256) {
        int r = idx / FIN, c = idx % FIN;
        int row = r0 + r;
        xsh[r][c] = (row < Nn) ? x0[row * FIN + c] : 0.f;
    }
    __syncthreads();
    for (int idx = tid; idx < 32 * Dd; idx += 256) {
        int r = idx / Dd, d = idx % Dd;
        float a = 0.f;
#pragma unroll
        for (int k = 0; k < FIN; k++) a += xsh[r][k] * Wenc[k * (Dd + 3) + d];
        float v = tanhf(a) * SCALE;
        zsh[r][d] = v;
        int row = r0 + r;
        if (row < Nn) g_z[row * Dd + d] = v;
    }
    __syncthreads();
    for (int idx = tid; idx < 32 * Dd; idx += 256) {
        int r = idx / Dd, d = idx % Dd;
        int row = r0 + r;
        if (row < Nn) {
            float a = 0.f;
#pragma unroll
            for (int k = 0; k < Dd; k++) a += zsh[r][k] * Wemb[k * Dd + d];
            g_XW1[row * Dd + d] = a;
        }
    }
    int p = tid;
    u64 wp[32];
#pragma unroll
    for (int kk = 0; kk < 32; kk++)
        wp[kk] = pk2(Wp[(2 * kk) * P1n + p], Wp[(2 * kk + 1) * P1n + p]);
    float se = 0.f, sev = 0.f;
    int rmax = Nn - r0; if (rmax > 32) rmax = 32;
    for (int r = 0; r < rmax; r++) {
        u64 acc = 0ull;
        const ulonglong2* zz = (const ulonglong2*)zsh[r];
#pragma unroll
        for (int q = 0; q < 16; q++) {
            ulonglong2 zp = zz[q];
            fma2(acc, zp.x, wp[2 * q]);
            fma2(acc, zp.y, wp[2 * q + 1]);
        }
        float v = sum2(acc) * SCALE;
        float e = __expf(v);
        g_E1[(r0 + r) * P1n + p] = e;
        se += e; sev += e * v;
    }
    atomicAdd(&g_colE[p], se);
    atomicAdd(&g_colEV[p], sev);
}

// ---------------- kernel 3: per-row dedup + sparse gathers + finalize + E1 pad zero ----------------
__global__ void __launch_bounds__(256) gather_fused() {
    if (blockIdx.x >= 1250) {
        if (blockIdx.x == 1250) {
            int p = threadIdx.x;
            float Z = g_colE[p];
            float iz = 1.f / Z;
            g_invZ[p] = iz;
            float ent = __logf(Z) - g_colEV[p] * iz;
            __shared__ float sh[8];
#pragma unroll
            for (int off = 16; off; off >>= 1) ent += __shfl_down_sync(0xffffffffu, ent, off);
            if ((p & 31) == 0) sh[p >> 5] = ent;
            __syncthreads();
            if (p == 0) {
                float s = 0.f;
                for (int w = 0; w < 8; w++) s += sh[w];
                atomicAdd(&g_acc[0], s * (1.f / ((float)Nn * (float)P1n)));
            }
        } else {
            // zero E1 pad rows (5000..5183): 184*256 floats over blocks 1251..1297
            int idx = (blockIdx.x - 1251) * 256 + threadIdx.x;
            if (idx < (E1ROWS - Nn) * P1n) g_E1[Nn * P1n + idx] = 0.f;
        }
        return;
    }
    int s = threadIdx.x >> 6;      // row slot 0..3
    int l = threadIdx.x & 63;      // lane in slot
    int i = blockIdx.x * 4 + s;
    __shared__ int cls[4][ELLW];
    __shared__ int scn[4];
    __shared__ int sdup[4];
    int cn = g_cnt[i]; if (cn > ELLW) cn = ELLW;
    if (l < cn) cls[s][l] = g_ell[i * ELLW + l];
    if (l == 0) sdup[s] = 0;
    __syncthreads();
    bool dup = false;
    if (l < cn) {
        int v = cls[s][l];
        for (int k = 0; k < l; k++) if (cls[s][k] == v) { dup = true; break; }
    }
    if (dup) sdup[s] = 1;
    __syncthreads();
    if (l == 0) {
        if (sdup[s]) {
            int w = 0;
            for (int k = 0; k < cn; k++) {
                int v = cls[s][k];
                bool d = false;
                for (int q = 0; q < w; q++) if (cls[s][q] == v) { d = true; break; }
                if (!d) cls[s][w++] = v;
            }
            scn[s] = w;
        } else scn[s] = cn;
    }
    __syncthreads();
    int n = scn[s];
    float4 as = make_float4(0.f, 0.f, 0.f, 0.f);
    float4 ax = make_float4(0.f, 0.f, 0.f, 0.f);
    int k = 0;
    for (; k + 2 <= n; k += 2) {
        int j0 = cls[s][k], j1 = cls[s][k + 1];
        float4 e0 = *(const float4*)&g_E1[j0 * P1n + 4 * l];
        float4 e1 = *(const float4*)&g_E1[j1 * P1n + 4 * l];
        as.x += e0.x + e1.x; as.y += e0.y + e1.y;
        as.z += e0.z + e1.z; as.w += e0.w + e1.w;
        if (l < 16) {
            float4 a0 = *(const float4*)&g_XW1[j0 * Dd + 4 * l];
            float4 a1 = *(const float4*)&g_XW1[j1 * Dd + 4 * l];
            ax.x += a0.x + a1.x; ax.y += a0.y + a1.y;
            ax.z += a0.z + a1.z; ax.w += a0.w + a1.w;
        }
    }
    if (k < n) {
        int j0 = cls[s][k];
        float4 e0 = *(const float4*)&g_E1[j0 * P1n + 4 * l];
        as.x += e0.x; as.y += e0.y; as.z += e0.z; as.w += e0.w;
        if (l < 16) {
            float4 a0 = *(const float4*)&g_XW1[j0 * Dd + 4 * l];
            ax.x += a0.x; ax.y += a0.y; ax.z += a0.z; ax.w += a0.w;
        }
    }
    *(float4*)&g_AS1[i * P1n + 4 * l] = as;
    if (l < 16)
        *(float4*)&g_ze1[i * Dd + 4 * l] =
            make_float4(tanhf(ax.x), tanhf(ax.y), tanhf(ax.z), tanhf(ax.w));
}

// ---------------- decoder core (zsh/ysh already populated) ----------------
__device__ void dec_core(float (*zsh)[Dd], const float* ysh,
                         const float* __restrict__ W1, const float* __restrict__ W2,
                         const float* __restrict__ b2, float* __restrict__ out) {
    __shared__ float2 sUR[8][8];
    __shared__ float pd[8], pr2[8];
    int h = threadIdx.x;
    float c = g_c[h];
    u64 acc2[8];
#pragma unroll
    for (int r = 0; r < 8; r++) acc2[r] = 0ull;
#pragma unroll 8
    for (int jj = 0; jj < 32; jj++) {
        u64 wp = pk2(W1[(9 + 2 * jj) * Hh + h], W1[(10 + 2 * jj) * Hh + h]);
#pragma unroll
        for (int r = 0; r < 8; r++) {
            u64 zp = *(const u64*)&zsh[r][2 * jj];
            fma2(acc2[r], zp, wp);
        }
    }
    float w2 = W2[h], w0 = g_w0[h], q = g_q[h];
    int wid = h >> 5, lane = h & 31;
#pragma unroll
    for (int r = 0; r < 8; r++) {
        float a = c + sum2(acc2[r]);
        float th = tanhf(a);
        float s = 1.f - th * th;
        float up = w2 * th;
        float rp = w2 * s * (w0 + 2.f * th * q);
#pragma unroll
        for (int off = 16; off; off >>= 1) {
            up += __shfl_down_sync(0xffffffffu, up, off);
            rp += __shfl_down_sync(0xffffffffu, rp, off);
        }
        if (lane == 0) sUR[r][wid] = make_float2(up, rp);
    }
    __syncthreads();
    if (h < 8) {
        float u = b2[0], rr = 0.f;
        for (int w = 0; w < 8; w++) { float2 v = sUR[h][w]; u += v.x; rr += v.y; }
        float dd = u - ysh[h];
        pd[h] = dd * dd;
        pr2[h] = rr * rr;
    }
    __syncthreads();
    if (h == 0) {
        float s1 = 0.f, s2 = 0.f;
        for (int r = 0; r < 8; r++) { s1 += pd[r]; s2 += pr2[r]; }
        atomicAdd(&g_acc[1], s1);
        atomicAdd(&g_acc[2], s2);
        __threadfence();
        unsigned int old = atomicAdd(&g_done, 1u);
        if (old == 660u) {
            float a0 = *(volatile float*)&g_acc[0];
            float a1 = *(volatile float*)&g_acc[1];
            float a2 = *(volatile float*)&g_acc[2];
            out[0] = (a1 + a2) * (1.f / (float)Mm) + a0;
        }
    }
}

// ---------------- decoder loader for z / x1 rows ----------------
__device__ void dec_zx(int base, const float* __restrict__ W1, const float* __restrict__ W2,
                       const float* __restrict__ b2, const float* __restrict__ yin,
                       float* __restrict__ out) {
    __shared__ __align__(16) float zsh[8][Dd];
    __shared__ float ysh[8];
    int h = threadIdx.x;
    for (int idx = h; idx < 8 * Dd; idx += 256) {
        int r = idx >> 6, j = idx & 63;
        int m = base + r;
        zsh[r][j] = (m < Nn) ? g_z[m * Dd + j] : g_x1[(m - Nn) * Dd + j];
    }
    if (h < 8) {
        int m = base + h;
        ysh[h] = (m < Nn) ? yin[m] : g_y1[m - Nn];
    }
    __syncthreads();
    dec_core(zsh, ysh, W1, W2, b2, out);
}

// ---------------- colgemm body (MLP=9 batched, unguarded E1) ----------------
template <int MODE>
__device__ void colgemm_body(int b, const float* __restrict__ yin) {
    int ks = b % KSPLIT, half = b / KSPLIT;
    int d0 = half * 32;
    int rbeg = ks * CHUNK;
    int n = Nn - rbeg; if (n > CHUNK) n = CHUNK; if (n < 0) n = 0;
    int tid = threadIdx.x;
    __shared__ __align__(16) float Bsh[CHUNK][32];
    __shared__ float ysh[CHUNK];
    const float* __restrict__ B = (MODE == 0) ? g_ze1 : g_U;
    for (int idx = tid; idx < CHUNK * 8; idx += 256) {
        int r = idx >> 3, q = idx & 7;
        float4 v = make_float4(0.f, 0.f, 0.f, 0.f);
        if (r < n) v = *(const float4*)&B[(rbeg + r) * Dd + d0 + q * 4];
        *(float4*)&Bsh[r][q * 4] = v;
    }
    if (MODE == 0 && half == 0 && tid < CHUNK)
        ysh[tid] = (tid < n) ? yin[rbeg + tid] : 0.f;
    __syncthreads();
    u64 acc2[16];
#pragma unroll
    for (int d = 0; d < 16; d++) acc2[d] = 0ull;
    float accY = 0.f;
    const float* __restrict__ ep = &g_E1[rbeg * P1n + tid];
#pragma unroll
    for (int b3 = 0; b3 < 3; b3++) {
        float a[9];
#pragma unroll
        for (int i = 0; i < 9; i++) a[i] = ep[i * P1n];   // pad rows are 0
        ep += 9 * P1n;
        int r0 = b3 * 9;
        if (MODE == 0 && half == 0) {
#pragma unroll
            for (int i = 0; i < 9; i++) accY += a[i] * ysh[r0 + i];
        }
#pragma unroll
        for (int i = 0; i < 9; i++) {
            u64 ap = pk2(a[i], a[i]);
            const ulonglong2* bb = (const ulonglong2*)&Bsh[r0 + i][0];
#pragma unroll
            for (int q = 0; q < 8; q++) {
                ulonglong2 v = bb[q];
                fma2(acc2[2 * q], v.x, ap);
                fma2(acc2[2 * q + 1], v.y, ap);
            }
        }
    }
    if (MODE == 0) {
        const float m = g_invZ[tid] * M1;
#pragma unroll
        for (int qq = 0; qq < 8; qq++) {
            float a, b2v, c, d;
            unpk(acc2[2 * qq], a, b2v);
            unpk(acc2[2 * qq + 1], c, d);
            red4(&g_x1[tid * Dd + d0 + 4 * qq], a * m, b2v * m, c * m, d * m);
        }
        if (half == 0) atomicAdd(&g_y1[tid], accY * m);
    } else {
#pragma unroll
        for (int qq = 0; qq < 8; qq++) {
            float a, b2v, c, d;
            unpk(acc2[2 * qq], a, b2v);
            unpk(acc2[2 * qq + 1], c, d);
            red4(&g_V[tid * Dd + d0 + 4 * qq], a, b2v, c, d);
        }
    }
}

// ---------------- lvl2 body: softmax2/S2 (b<32) + U GEMM (b 32..110) ----------------
__device__ void lvl2_body(int b, const float* __restrict__ Wp2) {
    int tid = threadIdx.x;
    if (b < P2n) {
        __shared__ float wcol[Dd];
        __shared__ float shE[8], shEV[8];
        __shared__ float sZ;
        if (tid < Dd) wcol[tid] = Wp2[tid * P2n + b];
        __syncthreads();
        float a = 0.f;
#pragma unroll
        for (int k = 0; k < Dd; k++) a += g_x1[tid * Dd + k] * wcol[k];
        float v = a * SCALE;
        float e = __expf(v);
        float se = e, sev = e * v;
#pragma unroll
        for (int off = 16; off; off >>= 1) {
            se += __shfl_down_sync(0xffffffffu, se, off);
            sev += __shfl_down_sync(0xffffffffu, sev, off);
        }
        if ((tid & 31) == 0) { shE[tid >> 5] = se; shEV[tid >> 5] = sev; }
        __syncthreads();
        if (tid == 0) {
            float Z = 0.f, EV = 0.f;
            for (int w = 0; w < 8; w++) { Z += shE[w]; EV += shEV[w]; }
            sZ = Z;
            atomicAdd(&g_acc[0], (__logf(Z) - EV / Z) * (1.f / ((float)P1n * (float)P2n)));
        }
        __syncthreads();
        g_S2[tid * P2n + b] = e / sZ;
        return;
    }
    int rb = (b - P2n) * 64;
    __shared__ __align__(16) float Xsh[32][Dd];
    __shared__ float Ash[64][33];
    int r = tid >> 2, cg = tid & 3;
    int c0 = cg * 16;
    u64 acc2[8];
#pragma unroll
    for (int q = 0; q < 8; q++) acc2[q] = 0ull;
    for (int kt = 0; kt < 8; kt++) {
        __syncthreads();
        for (int idx = tid; idx < 32 * Dd; idx += 256) {
            int kk = idx >> 6, j = idx & 63;
            Xsh[kk][j] = g_x1[(kt * 32 + kk) * Dd + j] * g_invZ[kt * 32 + kk];
        }
        for (int idx = tid; idx < 64 * 32; idx += 256) {
            int rr = idx >> 5, kk = idx & 31;
            int row = rb + rr;
            Ash[rr][kk] = (row < Nn) ? g_AS1[row * P1n + kt * 32 + kk] : 0.f;
        }
        __syncthreads();
#pragma unroll 4
        for (int kk = 0; kk < 32; kk++) {
            float a = Ash[r][kk];
            u64 ap = pk2(a, a);
            const u64* xs = (const u64*)&Xsh[kk][c0];
#pragma unroll
            for (int q = 0; q < 8; q++) fma2(acc2[q], xs[q], ap);
        }
    }
    int row = rb + r;
    if (row < Nn) {
#pragma unroll
        for (int q = 0; q < 4; q++) {
            float a, bb2, c, d;
            unpk(acc2[2 * q], a, bb2);
            unpk(acc2[2 * q + 1], c, d);
            *(float4*)&g_U[row * Dd + c0 + 4 * q] = make_float4(a, bb2, c, d);
        }
    }
}

// ---------------- node 4: colgemm0 (384) + decoder z rows 0..2495 (312) ----------------
__global__ void __launch_bounds__(256) k4(
    const float* __restrict__ yin, const float* __restrict__ W1,
    const float* __restrict__ W2, const float* __restrict__ b2,
    float* __restrict__ out) {
    if (blockIdx.x < 2 * KSPLIT) colgemm_body<0>(blockIdx.x, yin);
    else dec_zx((blockIdx.x - 2 * KSPLIT) * 8, W1, W2, b2, yin, out);
}

// ---------------- node 5: lvl2 (111) + decoder z rows 2496..4999 (313) ----------------
__global__ void __launch_bounds__(256) k5(
    const float* __restrict__ Wp2, const float* __restrict__ yin,
    const float* __restrict__ W1, const float* __restrict__ W2,
    const float* __restrict__ b2, float* __restrict__ out) {
    if (blockIdx.x < 111) lvl2_body(blockIdx.x, Wp2);
    else dec_zx(2496 + (blockIdx.x - 111) * 8, W1, W2, b2, yin, out);
}

// ---------------- node 6: colgemm1 (384) + decoder x1 rows (32) ----------------
__global__ void __launch_bounds__(256) k6(
    const float* __restrict__ yin, const float* __restrict__ W1,
    const float* __restrict__ W2, const float* __restrict__ b2,
    float* __restrict__ out) {
    if (blockIdx.x < 2 * KSPLIT) colgemm_body<1>(blockIdx.x, nullptr);
    else dec_zx(Nn + (blockIdx.x - 2 * KSPLIT) * 8, W1, W2, b2, yin, out);
}

// ---------------- node 7: decoder tail (4 blocks) with inline ze2 + pool2 ----------------
__global__ void __launch_bounds__(256) k7(
    const float* __restrict__ Wemb2, const float* __restrict__ W1,
    const float* __restrict__ W2, const float* __restrict__ b2,
    float* __restrict__ out) {
    int bb = blockIdx.x;      // 0..3 -> x2 rows bb*8 .. bb*8+7
    int tid = threadIdx.x;
    __shared__ float Wsh[64][Dd];      // Wemb2
    __shared__ float Vsh[32][Dd];      // scaled V tile
    __shared__ float Tsh[32][Dd];      // tanh tile (ze2 rows)
    __shared__ float S2sh[32][8];
    __shared__ __align__(16) float zsh[8][Dd];
    __shared__ float ysh[8];
    for (int idx = tid; idx < 64 * Dd; idx += 256) Wsh[idx >> 6][idx & 63] = Wemb2[idx];
    int j = tid & 63, p0 = tid >> 6;   // p0 in 0..3
    float accA = 0.f, accB = 0.f, yacc = 0.f;
    for (int kt = 0; kt < 8; kt++) {
        __syncthreads();
        for (int idx = tid; idx < 32 * Dd; idx += 256) {
            int kk = idx >> 6, d = idx & 63;
            Vsh[kk][d] = g_V[(kt * 32 + kk) * Dd + d] * g_invZ[kt * 32 + kk];
        }
        {
            int kk = tid >> 3, p = tid & 7;
            S2sh[kk][p] = g_S2[(kt * 32 + kk) * P2n + (bb * 8 + p)];
        }
        __syncthreads();
        for (int idx = tid; idx < 32 * Dd; idx += 256) {
            int kk = idx >> 6, jj = idx & 63;
            float s = 0.f;
#pragma unroll 8
            for (int d = 0; d < Dd; d++) s += Vsh[kk][d] * Wsh[d][jj];
            Tsh[kk][jj] = tanhf(s);
        }
        __syncthreads();
#pragma unroll 4
        for (int kk = 0; kk < 32; kk++) {
            float tv = Tsh[kk][j];
            accA += S2sh[kk][p0] * tv;
            accB += S2sh[kk][p0 + 4] * tv;
        }
        if (tid < 8) {
            float ya = 0.f;
            for (int kk = 0; kk < 32; kk++) ya += S2sh[kk][tid] * g_y1[kt * 32 + kk];
            yacc += ya;
        }
    }
    __syncthreads();
    const float scl = (float)P2n / (float)P1n;
    zsh[p0][j] = accA * scl;
    zsh[p0 + 4][j] = accB * scl;
    if (tid < 8) ysh[tid] = yacc * scl;
    __syncthreads();
    dec_core(zsh, ysh, W1, W2, b2, out);
}

// ---------------- launch: 7 serial nodes ----------------
extern "C" void kernel_launch(void* const* d_in, const int* in_sizes, int n_in,
                              void* d_out, int out_size) {
    const float* x0 = (const float*)d_in[0];
    const int* adj = (const int*)d_in[1];
    const float* t = (const float*)d_in[2];
    const float* y = (const float*)d_in[3];
    const float* Wenc = (const float*)d_in[4];
    const float* Wp1 = (const float*)d_in[5];
    const float* Wp2 = (const float*)d_in[6];
    const float* Wemb1 = (const float*)d_in[7];
    const float* Wemb2 = (const float*)d_in[8];
    const float* W1 = (const float*)d_in[9];
    const float* b1 = (const float*)d_in[10];
    const float* W2 = (const float*)d_in[11];
    const float* b2 = (const float*)d_in[12];
    float* out = (float*)d_out;

    prep<<<40, 256>>>(t, W1, b1);
    enc_edge<<<470, 256>>>(x0, Wenc, Wemb1, Wp1, adj);
    gather_fused<<<1251 + 47, 256>>>();
    k4<<<2 * KSPLIT + 312, 256>>>(y, W1, W2, b2, out);
    k5<<<111 + 313, 256>>>(Wp2, y, W1, W2, b2, out);
    k6<<<2 * KSPLIT + 32, 256>>>(y, W1, W2, b2, out);
    k7<<<4, 256>>>(Wemb2, W1, W2, b2, out);
}

// round 13
// speedup vs baseline: 1.0336x; 1.0336x over previous
#include <cuda_runtime.h>

#define Nn 5000
#define Ee 80000
#define FIN 32
#define Dd 64
#define P1n 256
#define P2n 32
#define Hh 256
#define Mm 5288
#define ELLW 64
#define SCALE 1.4763057f
#define M1 (256.f/5000.f)
#define KSPLIT 192
#define CHUNK 27
#define E1ROWS (KSPLIT * CHUNK)   // 5184 padded rows (pad rows never written -> zero-init)

typedef unsigned long long u64;

// ---------------- packed f32x2 helpers ----------------
__device__ __forceinline__ void fma2(u64& acc, u64 b, u64 a) {
    asm("fma.rn.f32x2 %0, %1, %2, %0;" : "+l"(acc) : "l"(b), "l"(a));
}
__device__ __forceinline__ u64 pk2(float lo, float hi) {
    u64 r; asm("mov.b64 %0, {%1, %2};" : "=l"(r) : "f"(lo), "f"(hi)); return r;
}
__device__ __forceinline__ void unpk(u64 v, float& a, float& b) {
    asm("mov.b64 {%0, %1}, %2;" : "=f"(a), "=f"(b) : "l"(v));
}
__device__ __forceinline__ float sum2(u64 v) {
    float a, b; unpk(v, a, b); return a + b;
}
__device__ __forceinline__ void red4(float* p, float a, float b, float c, float d) {
    asm volatile("red.global.add.v4.f32 [%0], {%1,%2,%3,%4};"
                 :: "l"(p), "f"(a), "f"(b), "f"(c), "f"(d) : "memory");
}

// ---------------- scratch (static, no allocation) ----------------
__device__ __align__(16) float g_z[Nn * Dd];
__device__ __align__(16) float g_XW1[Nn * Dd];
__device__ __align__(16) float g_E1[E1ROWS * P1n];  // exp(P1); pad rows stay 0
__device__ __align__(16) float g_ze1[Nn * Dd];
__device__ __align__(16) float g_W[5056 * Dd];      // E1 @ (D_iz x1)
__device__ __align__(16) float g_U[Nn * Dd];        // A @ W
__device__ int g_cnt[Nn];
__device__ int g_ell[Nn * ELLW];
__device__ float g_colE[P1n], g_colEV[P1n], g_invZ[P1n];
__device__ __align__(16) float g_x1[P1n * Dd];
__device__ float g_y1[P1n];
__device__ __align__(16) float g_V[P1n * Dd];       // E1^T U (unscaled)
__device__ __align__(16) float g_S2[P1n * P2n];
__device__ float g_c[Hh], g_q[Hh], g_w0[Hh];
__device__ float g_acc[4];   // [0]=ent, [1]=sum(u-y)^2, [2]=sum(res^2)
__device__ unsigned int g_done;

// ---------------- kernel 1: zero accumulators + decoder prep ----------------
__global__ void prep(const float* __restrict__ t, const float* __restrict__ W1,
                     const float* __restrict__ b1) {
    int i = blockIdx.x * blockDim.x + threadIdx.x;
    int st = gridDim.x * blockDim.x;
    for (int k = i; k < Nn; k += st) g_cnt[k] = 0;
    for (int k = i; k < P1n; k += st) { g_colE[k] = 0.f; g_colEV[k] = 0.f; g_y1[k] = 0.f; }
    for (int k = i; k < P1n * Dd; k += st) { g_x1[k] = 0.f; g_V[k] = 0.f; }
    if (i == 0) { g_acc[0] = g_acc[1] = g_acc[2] = g_acc[3] = 0.f; g_done = 0u; }
    if (blockIdx.x == 0) {
        int h = threadIdx.x;
        float t0 = t[0];
        float tx[6];
        tx[0] = t0 * 1e-2f;
        tx[1] = t0 * 1e-3f;
        tx[2] = t0 * 1e-4f;
        tx[3] = logf(t0 * 100.f + 1.f);
        tx[4] = logf(t0 * 10.f + 1.f);
        tx[5] = logf(t0 + 1.f);
        float c = b1[h];
#pragma unroll
        for (int k = 0; k < 6; k++) c += W1[k * Hh + h] * tx[k];
        float q = 0.f;
#pragma unroll
        for (int k = 1; k < 9; k++) { float w = W1[k * Hh + h]; q += w * w; }
        g_c[h] = c; g_q[h] = q; g_w0[h] = W1[h];
    }
}

// ---------------- kernel 2: encode (blocks 0..156) + edge ELL scatter ----------------
__global__ void __launch_bounds__(256) enc_edge(
    const float* __restrict__ x0, const float* __restrict__ Wenc,
    const float* __restrict__ Wemb, const float* __restrict__ Wp,
    const int* __restrict__ adj) {
    int tid = threadIdx.x;
    if (blockIdx.x >= 157) {
        int e = (blockIdx.x - 157) * 256 + tid;
        if (e < Ee) {
            int r0 = adj[e], r1 = adj[Ee + e];
            int pos = atomicAdd(&g_cnt[r0], 1);
            if (pos < ELLW) g_ell[r0 * ELLW + pos] = r1;
        }
        return;
    }
    __shared__ float xsh[32][FIN];
    __shared__ __align__(16) float zsh[32][Dd];
    int r0 = blockIdx.x * 32;
    for (int idx = tid; idx < 32 * FIN; idx += 256) {
        int r = idx / FIN, c = idx % FIN;
        int row = r0 + r;
        xsh[r][c] = (row < Nn) ? x0[row * FIN + c] : 0.f;
    }
    __syncthreads();
    for (int idx = tid; idx < 32 * Dd; idx += 256) {
        int r = idx / Dd, d = idx % Dd;
        float a = 0.f;
#pragma unroll
        for (int k = 0; k < FIN; k++) a += xsh[r][k] * Wenc[k * (Dd + 3) + d];
        float v = tanhf(a) * SCALE;
        zsh[r][d] = v;
        int row = r0 + r;
        if (row < Nn) g_z[row * Dd + d] = v;
    }
    __syncthreads();
    for (int idx = tid; idx < 32 * Dd; idx += 256) {
        int r = idx / Dd, d = idx % Dd;
        int row = r0 + r;
        if (row < Nn) {
            float a = 0.f;
#pragma unroll
            for (int k = 0; k < Dd; k++) a += zsh[r][k] * Wemb[k * Dd + d];
            g_XW1[row * Dd + d] = a;
        }
    }
    int p = tid;
    u64 wp[32];
#pragma unroll
    for (int kk = 0; kk < 32; kk++)
        wp[kk] = pk2(Wp[(2 * kk) * P1n + p], Wp[(2 * kk + 1) * P1n + p]);
    float se = 0.f, sev = 0.f;
    int rmax = Nn - r0; if (rmax > 32) rmax = 32;
    for (int r = 0; r < rmax; r++) {
        u64 acc = 0ull;
        const ulonglong2* zz = (const ulonglong2*)zsh[r];
#pragma unroll
        for (int q = 0; q < 16; q++) {
            ulonglong2 zp = zz[q];
            fma2(acc, zp.x, wp[2 * q]);
            fma2(acc, zp.y, wp[2 * q + 1]);
        }
        float v = sum2(acc) * SCALE;
        float e = __expf(v);
        g_E1[(r0 + r) * P1n + p] = e;
        se += e; sev += e * v;
    }
    atomicAdd(&g_colE[p], se);
    atomicAdd(&g_colEV[p], sev);
}

// ---------------- kernel 3: warp-per-row dedup (compact in place) + ze1 gather + finalize ----------------
// blocks 0..624: 8 rows each; block 625: finalize invZ + entropy
__global__ void __launch_bounds__(256) gather1() {
    if (blockIdx.x == 625) {
        int p = threadIdx.x;
        float Z = g_colE[p];
        float iz = 1.f / Z;
        g_invZ[p] = iz;
        float ent = __logf(Z) - g_colEV[p] * iz;
        __shared__ float sh[8];
#pragma unroll
        for (int off = 16; off; off >>= 1) ent += __shfl_down_sync(0xffffffffu, ent, off);
        if ((p & 31) == 0) sh[p >> 5] = ent;
        __syncthreads();
        if (p == 0) {
            float s = 0.f;
            for (int w = 0; w < 8; w++) s += sh[w];
            atomicAdd(&g_acc[0], s * (1.f / ((float)Nn * (float)P1n)));
        }
        return;
    }
    int w = threadIdx.x >> 5, lane = threadIdx.x & 31;
    int i = blockIdx.x * 8 + w;
    __shared__ int wl[8][ELLW];
    int cn = g_cnt[i]; if (cn > ELLW) cn = ELLW;
    if (lane < cn) wl[w][lane] = g_ell[i * ELLW + lane];
    if (lane + 32 < cn) wl[w][lane + 32] = g_ell[i * ELLW + lane + 32];
    __syncwarp();
    bool d0 = false, d1 = false;
    if (lane < cn) {
        int v = wl[w][lane];
        for (int k = 0; k < lane; k++) if (wl[w][k] == v) { d0 = true; break; }
    }
    if (lane + 32 < cn) {
        int v = wl[w][lane + 32];
        for (int k = 0; k < lane + 32; k++) if (wl[w][k] == v) { d1 = true; break; }
    }
    unsigned anyd = __ballot_sync(0xffffffffu, d0 || d1);
    int n = cn;
    if (anyd) {
        int wcnt = 0;
        if (lane == 0) {  // rare: serial compact + writeback for gather2
            for (int k = 0; k < cn; k++) {
                int v = wl[w][k];
                bool d = false;
                for (int q = 0; q < wcnt; q++) if (wl[w][q] == v) { d = true; break; }
                if (!d) wl[w][wcnt++] = v;
            }
            g_cnt[i] = wcnt;
            for (int k = 0; k < wcnt; k++) g_ell[i * ELLW + k] = wl[w][k];
        }
        n = __shfl_sync(0xffffffffu, wcnt, 0);
        __syncwarp();
    }
    float ax = 0.f, ay = 0.f;
    int k = 0;
    for (; k + 4 <= n; k += 4) {
        int j0 = wl[w][k], j1 = wl[w][k + 1], j2 = wl[w][k + 2], j3 = wl[w][k + 3];
        float2 a0 = *(const float2*)&g_XW1[j0 * Dd + 2 * lane];
        float2 a1 = *(const float2*)&g_XW1[j1 * Dd + 2 * lane];
        float2 a2 = *(const float2*)&g_XW1[j2 * Dd + 2 * lane];
        float2 a3 = *(const float2*)&g_XW1[j3 * Dd + 2 * lane];
        ax += (a0.x + a1.x) + (a2.x + a3.x);
        ay += (a0.y + a1.y) + (a2.y + a3.y);
    }
    for (; k < n; k++) {
        int j0 = wl[w][k];
        float2 a0 = *(const float2*)&g_XW1[j0 * Dd + 2 * lane];
        ax += a0.x; ay += a0.y;
    }
    *(float2*)&g_ze1[i * Dd + 2 * lane] = make_float2(tanhf(ax), tanhf(ay));
}

// ---------------- colgemm body (MLP=9 batched, unguarded E1; pad rows are zero) ----------------
template <int MODE>
__device__ void colgemm_body(int b, const float* __restrict__ yin) {
    int ks = b % KSPLIT, half = b / KSPLIT;
    int d0 = half * 32;
    int rbeg = ks * CHUNK;
    int n = Nn - rbeg; if (n > CHUNK) n = CHUNK; if (n < 0) n = 0;
    int tid = threadIdx.x;
    __shared__ __align__(16) float Bsh[CHUNK][32];
    __shared__ float ysh[CHUNK];
    const float* __restrict__ B = (MODE == 0) ? g_ze1 : g_U;
    for (int idx = tid; idx < CHUNK * 8; idx += 256) {
        int r = idx >> 3, q = idx & 7;
        float4 v = make_float4(0.f, 0.f, 0.f, 0.f);
        if (r < n) v = *(const float4*)&B[(rbeg + r) * Dd + d0 + q * 4];
        *(float4*)&Bsh[r][q * 4] = v;
    }
    if (MODE == 0 && half == 0 && tid < CHUNK)
        ysh[tid] = (tid < n) ? yin[rbeg + tid] : 0.f;
    __syncthreads();
    u64 acc2[16];
#pragma unroll
    for (int d = 0; d < 16; d++) acc2[d] = 0ull;
    float accY = 0.f;
    const float* __restrict__ ep = &g_E1[rbeg * P1n + tid];
#pragma unroll
    for (int b3 = 0; b3 < 3; b3++) {
        float a[9];
#pragma unroll
        for (int i = 0; i < 9; i++) a[i] = ep[i * P1n];   // pad rows are 0
        ep += 9 * P1n;
        int r0 = b3 * 9;
        if (MODE == 0 && half == 0) {
#pragma unroll
            for (int i = 0; i < 9; i++) accY += a[i] * ysh[r0 + i];
        }
#pragma unroll
        for (int i = 0; i < 9; i++) {
            u64 ap = pk2(a[i], a[i]);
            const ulonglong2* bb = (const ulonglong2*)&Bsh[r0 + i][0];
#pragma unroll
            for (int q = 0; q < 8; q++) {
                ulonglong2 v = bb[q];
                fma2(acc2[2 * q], v.x, ap);
                fma2(acc2[2 * q + 1], v.y, ap);
            }
        }
    }
    if (MODE == 0) {
        const float m = g_invZ[tid] * M1;
#pragma unroll
        for (int qq = 0; qq < 8; qq++) {
            float a, b2v, c, d;
            unpk(acc2[2 * qq], a, b2v);
            unpk(acc2[2 * qq + 1], c, d);
            red4(&g_x1[tid * Dd + d0 + 4 * qq], a * m, b2v * m, c * m, d * m);
        }
        if (half == 0) atomicAdd(&g_y1[tid], accY * m);
    } else {
#pragma unroll
        for (int qq = 0; qq < 8; qq++) {
            float a, b2v, c, d;
            unpk(acc2[2 * qq], a, b2v);
            unpk(acc2[2 * qq + 1], c, d);
            red4(&g_V[tid * Dd + d0 + 4 * qq], a, b2v, c, d);
        }
    }
}

template <int MODE>
__global__ void __launch_bounds__(256) colgemm(const float* __restrict__ yin) {
    colgemm_body<MODE>(blockIdx.x, yin);
}

// ---------------- kernel 5: softmax2/S2 (blocks 0..31) + W = E1 @ (D_iz x1) (32..110) ----------------
__global__ void __launch_bounds__(256) lvl2(const float* __restrict__ Wp2) {
    int b = blockIdx.x;
    int tid = threadIdx.x;
    if (b < P2n) {
        __shared__ float wcol[Dd];
        __shared__ float shE[8], shEV[8];
        __shared__ float sZ;
        if (tid < Dd) wcol[tid] = Wp2[tid * P2n + b];
        __syncthreads();
        float a = 0.f;
#pragma unroll
        for (int k = 0; k < Dd; k++) a += g_x1[tid * Dd + k] * wcol[k];
        float v = a * SCALE;
        float e = __expf(v);
        float se = e, sev = e * v;
#pragma unroll
        for (int off = 16; off; off >>= 1) {
            se += __shfl_down_sync(0xffffffffu, se, off);
            sev += __shfl_down_sync(0xffffffffu, sev, off);
        }
        if ((tid & 31) == 0) { shE[tid >> 5] = se; shEV[tid >> 5] = sev; }
        __syncthreads();
        if (tid == 0) {
            float Z = 0.f, EV = 0.f;
            for (int w = 0; w < 8; w++) { Z += shE[w]; EV += shEV[w]; }
            sZ = Z;
            atomicAdd(&g_acc[0], (__logf(Z) - EV / Z) * (1.f / ((float)P1n * (float)P2n)));
        }
        __syncthreads();
        g_S2[tid * P2n + b] = e / sZ;
        return;
    }
    int rb = (b - P2n) * 64;
    __shared__ __align__(16) float Xsh[32][Dd];
    __shared__ float Esh[64][33];
    int r = tid >> 2, cg = tid & 3;
    int c0 = cg * 16;
    u64 acc2[8];
#pragma unroll
    for (int q = 0; q < 8; q++) acc2[q] = 0ull;
    for (int kt = 0; kt < 8; kt++) {
        __syncthreads();
        for (int idx = tid; idx < 32 * Dd; idx += 256) {
            int kk = idx >> 6, j = idx & 63;
            Xsh[kk][j] = g_x1[(kt * 32 + kk) * Dd + j] * g_invZ[kt * 32 + kk];
        }
        for (int idx = tid; idx < 64 * 32; idx += 256) {
            int rr = idx >> 5, kk = idx & 31;
            Esh[rr][kk] = g_E1[(rb + rr) * P1n + kt * 32 + kk];  // pad rows are 0
        }
        __syncthreads();
#pragma unroll 4
        for (int kk = 0; kk < 32; kk++) {
            float a = Esh[r][kk];
            u64 ap = pk2(a, a);
            const u64* xs = (const u64*)&Xsh[kk][c0];
#pragma unroll
            for (int q = 0; q < 8; q++) fma2(acc2[q], xs[q], ap);
        }
    }
#pragma unroll
    for (int q = 0; q < 4; q++) {
        float a, bb2, c, d;
        unpk(acc2[2 * q], a, bb2);
        unpk(acc2[2 * q + 1], c, d);
        *(float4*)&g_W[(rb + r) * Dd + c0 + 4 * q] = make_float4(a, bb2, c, d);
    }
}

// ---------------- decoder core ----------------
__device__ void dec_core(float (*zsh)[Dd], const float* ysh,
                         const float* __restrict__ W1, const float* __restrict__ W2,
                         const float* __restrict__ b2, float* __restrict__ out) {
    __shared__ float2 sUR[8][8];
    __shared__ float pd[8], pr2[8];
    int h = threadIdx.x;
    float c = g_c[h];
    u64 acc2[8];
#pragma unroll
    for (int r = 0; r < 8; r++) acc2[r] = 0ull;
#pragma unroll 8
    for (int jj = 0; jj < 32; jj++) {
        u64 wp = pk2(W1[(9 + 2 * jj) * Hh + h], W1[(10 + 2 * jj) * Hh + h]);
#pragma unroll
        for (int r = 0; r < 8; r++) {
            u64 zp = *(const u64*)&zsh[r][2 * jj];
            fma2(acc2[r], zp, wp);
        }
    }
    float w2 = W2[h], w0 = g_w0[h], q = g_q[h];
    int wid = h >> 5, lane = h & 31;
#pragma unroll
    for (int r = 0; r < 8; r++) {
        float a = c + sum2(acc2[r]);
        float th = tanhf(a);
        float s = 1.f - th * th;
        float up = w2 * th;
        float rp = w2 * s * (w0 + 2.f * th * q);
#pragma unroll
        for (int off = 16; off; off >>= 1) {
            up += __shfl_down_sync(0xffffffffu, up, off);
            rp += __shfl_down_sync(0xffffffffu, rp, off);
        }
        if (lane == 0) sUR[r][wid] = make_float2(up, rp);
    }
    __syncthreads();
    if (h < 8) {
        float u = b2[0], rr = 0.f;
        for (int w = 0; w < 8; w++) { float2 v = sUR[h][w]; u += v.x; rr += v.y; }
        float dd = u - ysh[h];
        pd[h] = dd * dd;
        pr2[h] = rr * rr;
    }
    __syncthreads();
    if (h == 0) {
        float s1 = 0.f, s2 = 0.f;
        for (int r = 0; r < 8; r++) { s1 += pd[r]; s2 += pr2[r]; }
        atomicAdd(&g_acc[1], s1);
        atomicAdd(&g_acc[2], s2);
        __threadfence();
        unsigned int old = atomicAdd(&g_done, 1u);
        if (old == 660u) {
            float a0 = *(volatile float*)&g_acc[0];
            float a1 = *(volatile float*)&g_acc[1];
            float a2 = *(volatile float*)&g_acc[2];
            out[0] = (a1 + a2) * (1.f / (float)Mm) + a0;
        }
    }
}

__device__ void dec_zx(int base, const float* __restrict__ W1, const float* __restrict__ W2,
                       const float* __restrict__ b2, const float* __restrict__ yin,
                       float* __restrict__ out) {
    __shared__ __align__(16) float zsh[8][Dd];
    __shared__ float ysh[8];
    int h = threadIdx.x;
    for (int idx = h; idx < 8 * Dd; idx += 256) {
        int r = idx >> 6, j = idx & 63;
        int m = base + r;
        zsh[r][j] = (m < Nn) ? g_z[m * Dd + j] : g_x1[(m - Nn) * Dd + j];
    }
    if (h < 8) {
        int m = base + h;
        ysh[h] = (m < Nn) ? yin[m] : g_y1[m - Nn];
    }
    __syncthreads();
    dec_core(zsh, ysh, W1, W2, b2, out);
}

// ---------------- kernel 6: gather2 (U = A @ W, blocks 0..624) + decoder main (625..1281) ----------------
__global__ void __launch_bounds__(256) g2dec(
    const float* __restrict__ yin, const float* __restrict__ W1,
    const float* __restrict__ W2, const float* __restrict__ b2,
    float* __restrict__ out) {
    if (blockIdx.x >= 625) {
        dec_zx((blockIdx.x - 625) * 8, W1, W2, b2, yin, out);
        return;
    }
    int w = threadIdx.x >> 5, lane = threadIdx.x & 31;
    int i = blockIdx.x * 8 + w;
    __shared__ int wl[8][ELLW];
    int n = g_cnt[i]; if (n > ELLW) n = ELLW;   // already deduped by gather1
    if (lane < n) wl[w][lane] = g_ell[i * ELLW + lane];
    if (lane + 32 < n) wl[w][lane + 32] = g_ell[i * ELLW + lane + 32];
    __syncwarp();
    float ax = 0.f, ay = 0.f;
    int k = 0;
    for (; k + 4 <= n; k += 4) {
        int j0 = wl[w][k], j1 = wl[w][k + 1], j2 = wl[w][k + 2], j3 = wl[w][k + 3];
        float2 a0 = *(const float2*)&g_W[j0 * Dd + 2 * lane];
        float2 a1 = *(const float2*)&g_W[j1 * Dd + 2 * lane];
        float2 a2 = *(const float2*)&g_W[j2 * Dd + 2 * lane];
        float2 a3 = *(const float2*)&g_W[j3 * Dd + 2 * lane];
        ax += (a0.x + a1.x) + (a2.x + a3.x);
        ay += (a0.y + a1.y) + (a2.y + a3.y);
    }
    for (; k < n; k++) {
        int j0 = wl[w][k];
        float2 a0 = *(const float2*)&g_W[j0 * Dd + 2 * lane];
        ax += a0.x; ay += a0.y;
    }
    *(float2*)&g_U[i * Dd + 2 * lane] = make_float2(ax, ay);
}

// ---------------- kernel 8: decoder tail (4 blocks) with inline ze2 + pool2 ----------------
__global__ void __launch_bounds__(256) k7(
    const float* __restrict__ Wemb2, const float* __restrict__ W1,
    const float* __restrict__ W2, const float* __restrict__ b2,
    float* __restrict__ out) {
    int bb = blockIdx.x;      // 0..3 -> x2 rows bb*8 .. bb*8+7
    int tid = threadIdx.x;
    __shared__ float Wsh[64][Dd];
    __shared__ float Vsh[32][Dd];
    __shared__ float Tsh[32][Dd];
    __shared__ float S2sh[32][8];
    __shared__ __align__(16) float zsh[8][Dd];
    __shared__ float ysh[8];
    for (int idx = tid; idx < 64 * Dd; idx += 256) Wsh[idx >> 6][idx & 63] = Wemb2[idx];
    int j = tid & 63, p0 = tid >> 6;
    float accA = 0.f, accB = 0.f, yacc = 0.f;
    for (int kt = 0; kt < 8; kt++) {
        __syncthreads();
        for (int idx = tid; idx < 32 * Dd; idx += 256) {
            int kk = idx >> 6, d = idx & 63;
            Vsh[kk][d] = g_V[(kt * 32 + kk) * Dd + d] * g_invZ[kt * 32 + kk];
        }
        {
            int kk = tid >> 3, p = tid & 7;
            S2sh[kk][p] = g_S2[(kt * 32 + kk) * P2n + (bb * 8 + p)];
        }
        __syncthreads();
        for (int idx = tid; idx < 32 * Dd; idx += 256) {
            int kk = idx >> 6, jj = idx & 63;
            float s = 0.f;
#pragma unroll 8
            for (int d = 0; d < Dd; d++) s += Vsh[kk][d] * Wsh[d][jj];
            Tsh[kk][jj] = tanhf(s);
        }
        __syncthreads();
#pragma unroll 4
        for (int kk = 0; kk < 32; kk++) {
            float tv = Tsh[kk][j];
            accA += S2sh[kk][p0] * tv;
            accB += S2sh[kk][p0 + 4] * tv;
        }
        if (tid < 8) {
            float ya = 0.f;
            for (int kk = 0; kk < 32; kk++) ya += S2sh[kk][tid] * g_y1[kt * 32 + kk];
            yacc += ya;
        }
    }
    __syncthreads();
    const float scl = (float)P2n / (float)P1n;
    zsh[p0][j] = accA * scl;
    zsh[p0 + 4][j] = accB * scl;
    if (tid < 8) ysh[tid] = yacc * scl;
    __syncthreads();
    dec_core(zsh, ysh, W1, W2, b2, out);
}

// ---------------- launch: 8 serial nodes ----------------
extern "C" void kernel_launch(void* const* d_in, const int* in_sizes, int n_in,
                              void* d_out, int out_size) {
    const float* x0 = (const float*)d_in[0];
    const int* adj = (const int*)d_in[1];
    const float* t = (const float*)d_in[2];
    const float* y = (const float*)d_in[3];
    const float* Wenc = (const float*)d_in[4];
    const float* Wp1 = (const float*)d_in[5];
    const float* Wp2 = (const float*)d_in[6];
    const float* Wemb1 = (const float*)d_in[7];
    const float* Wemb2 = (const float*)d_in[8];
    const float* W1 = (const float*)d_in[9];
    const float* b1 = (const float*)d_in[10];
    const float* W2 = (const float*)d_in[11];
    const float* b2 = (const float*)d_in[12];
    float* out = (float*)d_out;

    prep<<<40, 256>>>(t, W1, b1);
    enc_edge<<<470, 256>>>(x0, Wenc, Wemb1, Wp1, adj);
    gather1<<<626, 256>>>();
    colgemm<0><<<2 * KSPLIT, 256>>>(y);
    lvl2<<<111, 256>>>(Wp2);
    g2dec<<<1282, 256>>>(y, W1, W2, b2, out);
    colgemm<1><<<2 * KSPLIT, 256>>>(nullptr);
    k7<<<4, 256>>>(Wemb2, W1, W2, b2, out);
}

// round 14
// speedup vs baseline: 1.0542x; 1.0199x over previous
#include <cuda_runtime.h>

#define Nn 5000
#define Ee 80000
#define FIN 32
#define Dd 64
#define P1n 256
#define P2n 32
#define Hh 256
#define Mm 5288
#define ELLW 64
#define SCALE 1.4763057f
#define M1 (256.f/5000.f)
#define KSPLIT 192
#define CHUNK 27
#define E1ROWS (KSPLIT * CHUNK)   // 5184 padded rows (pad rows never written -> zero-init)

typedef unsigned long long u64;

// ---------------- packed f32x2 helpers ----------------
__device__ __forceinline__ void fma2(u64& acc, u64 b, u64 a) {
    asm("fma.rn.f32x2 %0, %1, %2, %0;" : "+l"(acc) : "l"(b), "l"(a));
}
__device__ __forceinline__ u64 pk2(float lo, float hi) {
    u64 r; asm("mov.b64 %0, {%1, %2};" : "=l"(r) : "f"(lo), "f"(hi)); return r;
}
__device__ __forceinline__ void unpk(u64 v, float& a, float& b) {
    asm("mov.b64 {%0, %1}, %2;" : "=f"(a), "=f"(b) : "l"(v));
}
__device__ __forceinline__ float sum2(u64 v) {
    float a, b; unpk(v, a, b); return a + b;
}
__device__ __forceinline__ void red4(float* p, float a, float b, float c, float d) {
    asm volatile("red.global.add.v4.f32 [%0], {%1,%2,%3,%4};"
                 :: "l"(p), "f"(a), "f"(b), "f"(c), "f"(d) : "memory");
}

// ---------------- scratch (static, no allocation) ----------------
__device__ __align__(16) float g_z[Nn * Dd];
__device__ __align__(16) float g_XW1[Nn * Dd];
__device__ __align__(16) float g_E1[E1ROWS * P1n];  // exp(P1); pad rows stay 0
__device__ __align__(16) float g_ze1[Nn * Dd];
__device__ __align__(16) float g_W[5056 * Dd];      // E1 @ (D_iz x1)
__device__ __align__(16) float g_U[Nn * Dd];        // A @ W
__device__ int g_cnt[Nn];
__device__ int g_ell[Nn * ELLW];
__device__ float g_colE[P1n], g_colEV[P1n], g_invZ[P1n];
__device__ __align__(16) float g_x1[P1n * Dd];
__device__ float g_y1[P1n];
__device__ __align__(16) float g_V[P1n * Dd];       // E1^T U (unscaled)
__device__ __align__(16) float g_S2[P1n * P2n];
__device__ float g_c[Hh], g_q[Hh], g_w0[Hh];
__device__ float g_acc[4];   // [0]=ent, [1]=sum(u-y)^2, [2]=sum(res^2)
__device__ unsigned int g_done;

// ---------------- kernel 1: zero accumulators + decoder prep ----------------
__global__ void prep(const float* __restrict__ t, const float* __restrict__ W1,
                     const float* __restrict__ b1) {
    int i = blockIdx.x * blockDim.x + threadIdx.x;
    int st = gridDim.x * blockDim.x;
    for (int k = i; k < Nn; k += st) g_cnt[k] = 0;
    for (int k = i; k < P1n; k += st) { g_colE[k] = 0.f; g_colEV[k] = 0.f; g_y1[k] = 0.f; }
    for (int k = i; k < P1n * Dd; k += st) { g_x1[k] = 0.f; g_V[k] = 0.f; }
    if (i == 0) { g_acc[0] = g_acc[1] = g_acc[2] = g_acc[3] = 0.f; g_done = 0u; }
    if (blockIdx.x == 0) {
        int h = threadIdx.x;
        float t0 = t[0];
        float tx[6];
        tx[0] = t0 * 1e-2f;
        tx[1] = t0 * 1e-3f;
        tx[2] = t0 * 1e-4f;
        tx[3] = logf(t0 * 100.f + 1.f);
        tx[4] = logf(t0 * 10.f + 1.f);
        tx[5] = logf(t0 + 1.f);
        float c = b1[h];
#pragma unroll
        for (int k = 0; k < 6; k++) c += W1[k * Hh + h] * tx[k];
        float q = 0.f;
#pragma unroll
        for (int k = 1; k < 9; k++) { float w = W1[k * Hh + h]; q += w * w; }
        g_c[h] = c; g_q[h] = q; g_w0[h] = W1[h];
    }
}

// ---------------- kernel 2: encode (blocks 0..156) + edge ELL scatter ----------------
__global__ void __launch_bounds__(256) enc_edge(
    const float* __restrict__ x0, const float* __restrict__ Wenc,
    const float* __restrict__ Wemb, const float* __restrict__ Wp,
    const int* __restrict__ adj) {
    int tid = threadIdx.x;
    if (blockIdx.x >= 157) {
        int e = (blockIdx.x - 157) * 256 + tid;
        if (e < Ee) {
            int r0 = adj[e], r1 = adj[Ee + e];
            int pos = atomicAdd(&g_cnt[r0], 1);
            if (pos < ELLW) g_ell[r0 * ELLW + pos] = r1;
        }
        return;
    }
    __shared__ float xsh[32][FIN];
    __shared__ __align__(16) float zsh[32][Dd];
    int r0 = blockIdx.x * 32;
    for (int idx = tid; idx < 32 * FIN; idx += 256) {
        int r = idx / FIN, c = idx % FIN;
        int row = r0 + r;
        xsh[r][c] = (row < Nn) ? x0[row * FIN + c] : 0.f;
    }
    __syncthreads();
    for (int idx = tid; idx < 32 * Dd; idx += 256) {
        int r = idx / Dd, d = idx % Dd;
        float a = 0.f;
#pragma unroll
        for (int k = 0; k < FIN; k++) a += xsh[r][k] * Wenc[k * (Dd + 3) + d];
        float v = tanhf(a) * SCALE;
        zsh[r][d] = v;
        int row = r0 + r;
        if (row < Nn) g_z[row * Dd + d] = v;
    }
    __syncthreads();
    for (int idx = tid; idx < 32 * Dd; idx += 256) {
        int r = idx / Dd, d = idx % Dd;
        int row = r0 + r;
        if (row < Nn) {
            float a = 0.f;
#pragma unroll
            for (int k = 0; k < Dd; k++) a += zsh[r][k] * Wemb[k * Dd + d];
            g_XW1[row * Dd + d] = a;
        }
    }
    int p = tid;
    u64 wp[32];
#pragma unroll
    for (int kk = 0; kk < 32; kk++)
        wp[kk] = pk2(Wp[(2 * kk) * P1n + p], Wp[(2 * kk + 1) * P1n + p]);
    float se = 0.f, sev = 0.f;
    int rmax = Nn - r0; if (rmax > 32) rmax = 32;
    for (int r = 0; r < rmax; r++) {
        u64 acc = 0ull;
        const ulonglong2* zz = (const ulonglong2*)zsh[r];
#pragma unroll
        for (int q = 0; q < 16; q++) {
            ulonglong2 zp = zz[q];
            fma2(acc, zp.x, wp[2 * q]);
            fma2(acc, zp.y, wp[2 * q + 1]);
        }
        float v = sum2(acc) * SCALE;
        float e = __expf(v);
        g_E1[(r0 + r) * P1n + p] = e;
        se += e; sev += e * v;
    }
    atomicAdd(&g_colE[p], se);
    atomicAdd(&g_colEV[p], sev);
}

// ---------------- decoder core ----------------
__device__ void dec_core(float (*zsh)[Dd], const float* ysh,
                         const float* __restrict__ W1, const float* __restrict__ W2,
                         const float* __restrict__ b2, float* __restrict__ out) {
    __shared__ float2 sUR[8][8];
    __shared__ float pd[8], pr2[8];
    int h = threadIdx.x;
    float c = g_c[h];
    u64 acc2[8];
#pragma unroll
    for (int r = 0; r < 8; r++) acc2[r] = 0ull;
#pragma unroll 8
    for (int jj = 0; jj < 32; jj++) {
        u64 wp = pk2(W1[(9 + 2 * jj) * Hh + h], W1[(10 + 2 * jj) * Hh + h]);
#pragma unroll
        for (int r = 0; r < 8; r++) {
            u64 zp = *(const u64*)&zsh[r][2 * jj];
            fma2(acc2[r], zp, wp);
        }
    }
    float w2 = W2[h], w0 = g_w0[h], q = g_q[h];
    int wid = h >> 5, lane = h & 31;
#pragma unroll
    for (int r = 0; r < 8; r++) {
        float a = c + sum2(acc2[r]);
        float th = tanhf(a);
        float s = 1.f - th * th;
        float up = w2 * th;
        float rp = w2 * s * (w0 + 2.f * th * q);
#pragma unroll
        for (int off = 16; off; off >>= 1) {
            up += __shfl_down_sync(0xffffffffu, up, off);
            rp += __shfl_down_sync(0xffffffffu, rp, off);
        }
        if (lane == 0) sUR[r][wid] = make_float2(up, rp);
    }
    __syncthreads();
    if (h < 8) {
        float u = b2[0], rr = 0.f;
        for (int w = 0; w < 8; w++) { float2 v = sUR[h][w]; u += v.x; rr += v.y; }
        float dd = u - ysh[h];
        pd[h] = dd * dd;
        pr2[h] = rr * rr;
    }
    __syncthreads();
    if (h == 0) {
        float s1 = 0.f, s2 = 0.f;
        for (int r = 0; r < 8; r++) { s1 += pd[r]; s2 += pr2[r]; }
        atomicAdd(&g_acc[1], s1);
        atomicAdd(&g_acc[2], s2);
        __threadfence();
        unsigned int old = atomicAdd(&g_done, 1u);
        if (old == 660u) {
            float a0 = *(volatile float*)&g_acc[0];
            float a1 = *(volatile float*)&g_acc[1];
            float a2 = *(volatile float*)&g_acc[2];
            out[0] = (a1 + a2) * (1.f / (float)Mm) + a0;
        }
    }
}

__device__ void dec_zx(int base, const float* __restrict__ W1, const float* __restrict__ W2,
                       const float* __restrict__ b2, const float* __restrict__ yin,
                       float* __restrict__ out) {
    __shared__ __align__(16) float zsh[8][Dd];
    __shared__ float ysh[8];
    int h = threadIdx.x;
    for (int idx = h; idx < 8 * Dd; idx += 256) {
        int r = idx >> 6, j = idx & 63;
        int m = base + r;
        zsh[r][j] = (m < Nn) ? g_z[m * Dd + j] : g_x1[(m - Nn) * Dd + j];
    }
    if (h < 8) {
        int m = base + h;
        ysh[h] = (m < Nn) ? yin[m] : g_y1[m - Nn];
    }
    __syncthreads();
    dec_core(zsh, ysh, W1, W2, b2, out);
}

// ---------------- kernel 3: dedup+ze1 gather (0..624) + finalize (625) + decoder z-rows (626..1250) ----------------
__global__ void __launch_bounds__(256) gather1(
    const float* __restrict__ yin, const float* __restrict__ W1,
    const float* __restrict__ W2, const float* __restrict__ b2,
    float* __restrict__ out) {
    if (blockIdx.x >= 626) {
        dec_zx((blockIdx.x - 626) * 8, W1, W2, b2, yin, out);
        return;
    }
    if (blockIdx.x == 625) {
        int p = threadIdx.x;
        float Z = g_colE[p];
        float iz = 1.f / Z;
        g_invZ[p] = iz;
        float ent = __logf(Z) - g_colEV[p] * iz;
        __shared__ float sh[8];
#pragma unroll
        for (int off = 16; off; off >>= 1) ent += __shfl_down_sync(0xffffffffu, ent, off);
        if ((p & 31) == 0) sh[p >> 5] = ent;
        __syncthreads();
        if (p == 0) {
            float s = 0.f;
            for (int w = 0; w < 8; w++) s += sh[w];
            atomicAdd(&g_acc[0], s * (1.f / ((float)Nn * (float)P1n)));
        }
        return;
    }
    int w = threadIdx.x >> 5, lane = threadIdx.x & 31;
    int i = blockIdx.x * 8 + w;
    __shared__ int wl[8][ELLW];
    int cn = g_cnt[i]; if (cn > ELLW) cn = ELLW;
    if (lane < cn) wl[w][lane] = g_ell[i * ELLW + lane];
    if (lane + 32 < cn) wl[w][lane + 32] = g_ell[i * ELLW + lane + 32];
    __syncwarp();
    bool d0 = false, d1 = false;
    if (lane < cn) {
        int v = wl[w][lane];
        for (int k = 0; k < lane; k++) if (wl[w][k] == v) { d0 = true; break; }
    }
    if (lane + 32 < cn) {
        int v = wl[w][lane + 32];
        for (int k = 0; k < lane + 32; k++) if (wl[w][k] == v) { d1 = true; break; }
    }
    unsigned anyd = __ballot_sync(0xffffffffu, d0 || d1);
    int n = cn;
    if (anyd) {
        int wcnt = 0;
        if (lane == 0) {  // rare: serial compact + writeback for gather2
            for (int k = 0; k < cn; k++) {
                int v = wl[w][k];
                bool d = false;
                for (int q = 0; q < wcnt; q++) if (wl[w][q] == v) { d = true; break; }
                if (!d) wl[w][wcnt++] = v;
            }
            g_cnt[i] = wcnt;
            for (int k = 0; k < wcnt; k++) g_ell[i * ELLW + k] = wl[w][k];
        }
        n = __shfl_sync(0xffffffffu, wcnt, 0);
        __syncwarp();
    }
    float ax = 0.f, ay = 0.f;
    int k = 0;
    for (; k + 4 <= n; k += 4) {
        int j0 = wl[w][k], j1 = wl[w][k + 1], j2 = wl[w][k + 2], j3 = wl[w][k + 3];
        float2 a0 = *(const float2*)&g_XW1[j0 * Dd + 2 * lane];
        float2 a1 = *(const float2*)&g_XW1[j1 * Dd + 2 * lane];
        float2 a2 = *(const float2*)&g_XW1[j2 * Dd + 2 * lane];
        float2 a3 = *(const float2*)&g_XW1[j3 * Dd + 2 * lane];
        ax += (a0.x + a1.x) + (a2.x + a3.x);
        ay += (a0.y + a1.y) + (a2.y + a3.y);
    }
    for (; k < n; k++) {
        int j0 = wl[w][k];
        float2 a0 = *(const float2*)&g_XW1[j0 * Dd + 2 * lane];
        ax += a0.x; ay += a0.y;
    }
    *(float2*)&g_ze1[i * Dd + 2 * lane] = make_float2(tanhf(ax), tanhf(ay));
}

// ---------------- colgemm: full 27-deep load batch (single scoreboard wait) ----------------
template <int MODE>
__global__ void __launch_bounds__(256) colgemm(const float* __restrict__ yin) {
    int ks = blockIdx.x % KSPLIT, half = blockIdx.x / KSPLIT;
    int d0 = half * 32;
    int rbeg = ks * CHUNK;
    int n = Nn - rbeg; if (n > CHUNK) n = CHUNK; if (n < 0) n = 0;
    int tid = threadIdx.x;
    __shared__ __align__(16) float Bsh[CHUNK][32];
    __shared__ float ysh[CHUNK];
    const float* __restrict__ B = (MODE == 0) ? g_ze1 : g_U;
    for (int idx = tid; idx < CHUNK * 8; idx += 256) {
        int r = idx >> 3, q = idx & 7;
        float4 v = make_float4(0.f, 0.f, 0.f, 0.f);
        if (r < n) v = *(const float4*)&B[(rbeg + r) * Dd + d0 + q * 4];
        *(float4*)&Bsh[r][q * 4] = v;
    }
    if (MODE == 0 && half == 0 && tid < CHUNK)
        ysh[tid] = (tid < n) ? yin[rbeg + tid] : 0.f;
    __syncthreads();
    // issue ALL 27 E1 loads up front (pad rows are zero; no guards)
    float a[CHUNK];
    {
        const float* __restrict__ ep = &g_E1[rbeg * P1n + tid];
#pragma unroll
        for (int i = 0; i < CHUNK; i++) a[i] = ep[i * P1n];
    }
    u64 acc2[16];
#pragma unroll
    for (int d = 0; d < 16; d++) acc2[d] = 0ull;
    float accY = 0.f;
    if (MODE == 0 && half == 0) {
#pragma unroll
        for (int i = 0; i < CHUNK; i++) accY += a[i] * ysh[i];
    }
#pragma unroll
    for (int i = 0; i < CHUNK; i++) {
        u64 ap = pk2(a[i], a[i]);
        const ulonglong2* bb = (const ulonglong2*)&Bsh[i][0];
#pragma unroll
        for (int q = 0; q < 8; q++) {
            ulonglong2 v = bb[q];
            fma2(acc2[2 * q], v.x, ap);
            fma2(acc2[2 * q + 1], v.y, ap);
        }
    }
    if (MODE == 0) {
        const float m = g_invZ[tid] * M1;
#pragma unroll
        for (int qq = 0; qq < 8; qq++) {
            float av, bv, cv, dv;
            unpk(acc2[2 * qq], av, bv);
            unpk(acc2[2 * qq + 1], cv, dv);
            red4(&g_x1[tid * Dd + d0 + 4 * qq], av * m, bv * m, cv * m, dv * m);
        }
        if (half == 0) atomicAdd(&g_y1[tid], accY * m);
    } else {
#pragma unroll
        for (int qq = 0; qq < 8; qq++) {
            float av, bv, cv, dv;
            unpk(acc2[2 * qq], av, bv);
            unpk(acc2[2 * qq + 1], cv, dv);
            red4(&g_V[tid * Dd + d0 + 4 * qq], av, bv, cv, dv);
        }
    }
}

// ---------------- kernel 5: softmax2/S2 (blocks 0..31) + W = E1 @ (D_iz x1) (32..110) ----------------
__global__ void __launch_bounds__(256) lvl2(const float* __restrict__ Wp2) {
    int b = blockIdx.x;
    int tid = threadIdx.x;
    if (b < P2n) {
        __shared__ float wcol[Dd];
        __shared__ float shE[8], shEV[8];
        __shared__ float sZ;
        if (tid < Dd) wcol[tid] = Wp2[tid * P2n + b];
        __syncthreads();
        float a = 0.f;
#pragma unroll
        for (int k = 0; k < Dd; k++) a += g_x1[tid * Dd + k] * wcol[k];
        float v = a * SCALE;
        float e = __expf(v);
        float se = e, sev = e * v;
#pragma unroll
        for (int off = 16; off; off >>= 1) {
            se += __shfl_down_sync(0xffffffffu, se, off);
            sev += __shfl_down_sync(0xffffffffu, sev, off);
        }
        if ((tid & 31) == 0) { shE[tid >> 5] = se; shEV[tid >> 5] = sev; }
        __syncthreads();
        if (tid == 0) {
            float Z = 0.f, EV = 0.f;
            for (int w = 0; w < 8; w++) { Z += shE[w]; EV += shEV[w]; }
            sZ = Z;
            atomicAdd(&g_acc[0], (__logf(Z) - EV / Z) * (1.f / ((float)P1n * (float)P2n)));
        }
        __syncthreads();
        g_S2[tid * P2n + b] = e / sZ;
        return;
    }
    int rb = (b - P2n) * 64;
    __shared__ __align__(16) float Xsh[32][Dd];
    __shared__ float Esh[64][33];
    int r = tid >> 2, cg = tid & 3;
    int c0 = cg * 16;
    u64 acc2[8];
#pragma unroll
    for (int q = 0; q < 8; q++) acc2[q] = 0ull;
    for (int kt = 0; kt < 8; kt++) {
        __syncthreads();
        for (int idx = tid; idx < 32 * Dd; idx += 256) {
            int kk = idx >> 6, j = idx & 63;
            Xsh[kk][j] = g_x1[(kt * 32 + kk) * Dd + j] * g_invZ[kt * 32 + kk];
        }
        for (int idx = tid; idx < 64 * 32; idx += 256) {
            int rr = idx >> 5, kk = idx & 31;
            Esh[rr][kk] = g_E1[(rb + rr) * P1n + kt * 32 + kk];  // pad rows are 0
        }
        __syncthreads();
#pragma unroll 4
        for (int kk = 0; kk < 32; kk++) {
            float a = Esh[r][kk];
            u64 ap = pk2(a, a);
            const u64* xs = (const u64*)&Xsh[kk][c0];
#pragma unroll
            for (int q = 0; q < 8; q++) fma2(acc2[q], xs[q], ap);
        }
    }
#pragma unroll
    for (int q = 0; q < 4; q++) {
        float a, bb2, c, d;
        unpk(acc2[2 * q], a, bb2);
        unpk(acc2[2 * q + 1], c, d);
        *(float4*)&g_W[(rb + r) * Dd + c0 + 4 * q] = make_float4(a, bb2, c, d);
    }
}

// ---------------- kernel 6: gather2 (U = A @ W, blocks 0..624) + decoder x1-rows (625..656) ----------------
__global__ void __launch_bounds__(256) g2dec(
    const float* __restrict__ yin, const float* __restrict__ W1,
    const float* __restrict__ W2, const float* __restrict__ b2,
    float* __restrict__ out) {
    if (blockIdx.x >= 625) {
        dec_zx(Nn + (blockIdx.x - 625) * 8, W1, W2, b2, yin, out);
        return;
    }
    int w = threadIdx.x >> 5, lane = threadIdx.x & 31;
    int i = blockIdx.x * 8 + w;
    __shared__ int wl[8][ELLW];
    int n = g_cnt[i]; if (n > ELLW) n = ELLW;   // already deduped by gather1
    if (lane < n) wl[w][lane] = g_ell[i * ELLW + lane];
    if (lane + 32 < n) wl[w][lane + 32] = g_ell[i * ELLW + lane + 32];
    __syncwarp();
    float ax = 0.f, ay = 0.f;
    int k = 0;
    for (; k + 4 <= n; k += 4) {
        int j0 = wl[w][k], j1 = wl[w][k + 1], j2 = wl[w][k + 2], j3 = wl[w][k + 3];
        float2 a0 = *(const float2*)&g_W[j0 * Dd + 2 * lane];
        float2 a1 = *(const float2*)&g_W[j1 * Dd + 2 * lane];
        float2 a2 = *(const float2*)&g_W[j2 * Dd + 2 * lane];
        float2 a3 = *(const float2*)&g_W[j3 * Dd + 2 * lane];
        ax += (a0.x + a1.x) + (a2.x + a3.x);
        ay += (a0.y + a1.y) + (a2.y + a3.y);
    }
    for (; k < n; k++) {
        int j0 = wl[w][k];
        float2 a0 = *(const float2*)&g_W[j0 * Dd + 2 * lane];
        ax += a0.x; ay += a0.y;
    }
    *(float2*)&g_U[i * Dd + 2 * lane] = make_float2(ax, ay);
}

// ---------------- kernel 8: decoder tail (4 blocks) with inline ze2 + pool2 ----------------
__global__ void __launch_bounds__(256) k7(
    const float* __restrict__ Wemb2, const float* __restrict__ W1,
    const float* __restrict__ W2, const float* __restrict__ b2,
    float* __restrict__ out) {
    int bb = blockIdx.x;      // 0..3 -> x2 rows bb*8 .. bb*8+7
    int tid = threadIdx.x;
    __shared__ float Wsh[64][Dd];
    __shared__ float Vsh[32][Dd];
    __shared__ float Tsh[32][Dd];
    __shared__ float S2sh[32][8];
    __shared__ __align__(16) float zsh[8][Dd];
    __shared__ float ysh[8];
    for (int idx = tid; idx < 64 * Dd; idx += 256) Wsh[idx >> 6][idx & 63] = Wemb2[idx];
    int j = tid & 63, p0 = tid >> 6;
    float accA = 0.f, accB = 0.f, yacc = 0.f;
    for (int kt = 0; kt < 8; kt++) {
        __syncthreads();
        for (int idx = tid; idx < 32 * Dd; idx += 256) {
            int kk = idx >> 6, d = idx & 63;
            Vsh[kk][d] = g_V[(kt * 32 + kk) * Dd + d] * g_invZ[kt * 32 + kk];
        }
        {
            int kk = tid >> 3, p = tid & 7;
            S2sh[kk][p] = g_S2[(kt * 32 + kk) * P2n + (bb * 8 + p)];
        }
        __syncthreads();
        for (int idx = tid; idx < 32 * Dd; idx += 256) {
            int kk = idx >> 6, jj = idx & 63;
            float s = 0.f;
#pragma unroll 8
            for (int d = 0; d < Dd; d++) s += Vsh[kk][d] * Wsh[d][jj];
            Tsh[kk][jj] = tanhf(s);
        }
        __syncthreads();
#pragma unroll 4
        for (int kk = 0; kk < 32; kk++) {
            float tv = Tsh[kk][j];
            accA += S2sh[kk][p0] * tv;
            accB += S2sh[kk][p0 + 4] * tv;
        }
        if (tid < 8) {
            float ya = 0.f;
            for (int kk = 0; kk < 32; kk++) ya += S2sh[kk][tid] * g_y1[kt * 32 + kk];
            yacc += ya;
        }
    }
    __syncthreads();
    const float scl = (float)P2n / (float)P1n;
    zsh[p0][j] = accA * scl;
    zsh[p0 + 4][j] = accB * scl;
    if (tid < 8) ysh[tid] = yacc * scl;
    __syncthreads();
    dec_core(zsh, ysh, W1, W2, b2, out);
}

// ---------------- launch: 8 serial nodes ----------------
extern "C" void kernel_launch(void* const* d_in, const int* in_sizes, int n_in,
                              void* d_out, int out_size) {
    const float* x0 = (const float*)d_in[0];
    const int* adj = (const int*)d_in[1];
    const float* t = (const float*)d_in[2];
    const float* y = (const float*)d_in[3];
    const float* Wenc = (const float*)d_in[4];
    const float* Wp1 = (const float*)d_in[5];
    const float* Wp2 = (const float*)d_in[6];
    const float* Wemb1 = (const float*)d_in[7];
    const float* Wemb2 = (const float*)d_in[8];
    const float* W1 = (const float*)d_in[9];
    const float* b1 = (const float*)d_in[10];
    const float* W2 = (const float*)d_in[11];
    const float* b2 = (const float*)d_in[12];
    float* out = (float*)d_out;

    prep<<<40, 256>>>(t, W1, b1);
    enc_edge<<<470, 256>>>(x0, Wenc, Wemb1, Wp1, adj);
    gather1<<<626 + 625, 256>>>(y, W1, W2, b2, out);
    colgemm<0><<<2 * KSPLIT, 256>>>(y);
    lvl2<<<111, 256>>>(Wp2);
    g2dec<<<625 + 32, 256>>>(y, W1, W2, b2, out);
    colgemm<1><<<2 * KSPLIT, 256>>>(nullptr);
    k7<<<4, 256>>>(Wemb2, W1, W2, b2, out);
}